// round 1
// baseline (speedup 1.0000x reference)
#include <cuda_runtime.h>
#include <cuda_bf16.h>

// ---------------------------------------------------------------------------
// OctreeInterp: trilinear interpolation over sparse octree nodes.
//
// Strategy: replace the per-corner binary search (18 dependent probes) with a
// dense inverse-lookup table key -> node index (-1 = empty). Table is 4B *
// R^3 = 1 MB at depth 6; resident in L2. Rebuilt every launch (clear+scatter)
// so the graph replay is deterministic. Binary-search fallback for keys
// outside the table range (batch != 0 or depth > 8).
// ---------------------------------------------------------------------------

#define TABLE_MAX (1 << 24)   // supports depth <= 8 (R^3 = 2^24); 64 MB BSS
__device__ int g_table[TABLE_MAX];

__global__ void clear_table_k(const int* __restrict__ depth_p) {
    int depth = *depth_p;
    long long R3 = 1LL << (3 * depth);
    long long n = R3 < (long long)TABLE_MAX ? R3 : (long long)TABLE_MAX;
    long long stride = (long long)gridDim.x * blockDim.x;
    for (long long i = (long long)blockIdx.x * blockDim.x + threadIdx.x; i < n; i += stride)
        g_table[i] = -1;
}

__global__ void build_table_k(const int* __restrict__ keys, int nnum,
                              const int* __restrict__ depth_p) {
    int depth = *depth_p;
    long long lim = 1LL << (3 * depth);
    if (lim > (long long)TABLE_MAX) lim = (long long)TABLE_MAX;
    int stride = gridDim.x * blockDim.x;
    for (int i = blockIdx.x * blockDim.x + threadIdx.x; i < nnum; i += stride) {
        int k = keys[i];
        if (k >= 0 && (long long)k < lim) g_table[k] = i;   // keys unique: no race
    }
}

// key -> node index (or -1). Fast path: dense table. Fallback: binary search
// (lower_bound semantics, matching jnp.searchsorted 'left').
__device__ __forceinline__ int lookup_idx(int key, const int* __restrict__ keys,
                                          int nnum, long long table_lim) {
    if (key >= 0 && (long long)key < table_lim)
        return g_table[key];
    int lo = 0, hi = nnum;
    while (lo < hi) {
        int mid = (lo + hi) >> 1;
        if (keys[mid] < key) lo = mid + 1; else hi = mid;
    }
    return (lo < nnum && keys[lo] == key) ? lo : -1;
}

// Vectorized main kernel: blockDim = (cgroups, pts_per_block).
// threadIdx.x = float4 channel group, threadIdx.y = point slot.
// Each corner gather = cgroups * 16 B contiguous (128 B for C=32).
__global__ void interp_vec_k(const float4* __restrict__ data4,
                             const float4* __restrict__ pts4,
                             const int* __restrict__ keys, int nnum,
                             const int* __restrict__ depth_p,
                             float4* __restrict__ out4,
                             int npts, int cgroups) {
    int cg = threadIdx.x;
    int p  = blockIdx.x * blockDim.y + threadIdx.y;
    if (p >= npts) return;

    int depth = *depth_p;                       // uniform load, L1-resident
    int R = 1 << depth;
    long long R3 = 1LL << (3 * depth);
    long long table_lim = R3 < (long long)TABLE_MAX ? R3 : (long long)TABLE_MAX;
    float scale = (float)(1 << (depth - 1));

    float4 pt = pts4[p];
    int b = (int)pt.w;                          // astype(int32): trunc toward 0

    // xyzf = (xyz + 1) * scale - 0.5 ; xyzi = floor ; frac = xyzf - xyzi
    float xf = (pt.x + 1.0f) * scale - 0.5f;
    float yf = (pt.y + 1.0f) * scale - 0.5f;
    float zf = (pt.z + 1.0f) * scale - 0.5f;
    float fxi = floorf(xf), fyi = floorf(yf), fzi = floorf(zf);
    int xi = (int)fxi, yi = (int)fyi, zi = (int)fzi;
    float frx = xf - fxi, fry = yf - fyi, frz = zf - fzi;

    // Phase 1: keys + table lookups for all 8 corners (batched for MLP)
    int   idxs[8];
    float ws[8];
#pragma unroll
    for (int g = 0; g < 8; g++) {
        int gx = (g >> 2) & 1, gy = (g >> 1) & 1, gz = g & 1;
        int cx = xi + gx, cy = yi + gy, cz = zi + gz;
        bool inb = (cx >= 0) & (cx < R) & (cy >= 0) & (cy < R) & (cz >= 0) & (cz < R);
        // weight |prod(1 - grid - frac)| = prod(gbit ? frac : 1-frac)
        float w = (gx ? frx : 1.0f - frx) *
                  (gy ? fry : 1.0f - fry) *
                  (gz ? frz : 1.0f - frz);
        int key = ((b * R + cx) * R + cy) * R + cz;   // int32, matches jnp
        idxs[g] = inb ? lookup_idx(key, keys, nnum, table_lim) : -1;
        ws[g]   = w;
    }

    // Phase 2: gathers + weighted accumulate
    float4 acc = make_float4(0.f, 0.f, 0.f, 0.f);
    float wsum = 0.f;
#pragma unroll
    for (int g = 0; g < 8; g++) {
        int idx = idxs[g];
        if (idx >= 0) {
            float w = ws[g];
            float4 v = data4[(size_t)idx * cgroups + cg];
            acc.x += w * v.x; acc.y += w * v.y;
            acc.z += w * v.z; acc.w += w * v.w;
            wsum += w;
        }
    }

    float inv = 1.0f / (wsum + 1e-12f);
    acc.x *= inv; acc.y *= inv; acc.z *= inv; acc.w *= inv;
    out4[(size_t)p * cgroups + cg] = acc;
}

// Scalar fallback for C not divisible by 4: one thread per (point, channel).
__global__ void interp_scalar_k(const float* __restrict__ data,
                                const float* __restrict__ pts,
                                const int* __restrict__ keys, int nnum,
                                const int* __restrict__ depth_p,
                                float* __restrict__ out,
                                int npts, int C) {
    long long t = (long long)blockIdx.x * blockDim.x + threadIdx.x;
    long long total = (long long)npts * C;
    if (t >= total) return;
    int p = (int)(t / C);
    int c = (int)(t % C);

    int depth = *depth_p;
    int R = 1 << depth;
    long long R3 = 1LL << (3 * depth);
    long long table_lim = R3 < (long long)TABLE_MAX ? R3 : (long long)TABLE_MAX;
    float scale = (float)(1 << (depth - 1));

    const float* pp = pts + (size_t)p * 4;
    float xf = (pp[0] + 1.0f) * scale - 0.5f;
    float yf = (pp[1] + 1.0f) * scale - 0.5f;
    float zf = (pp[2] + 1.0f) * scale - 0.5f;
    int b = (int)pp[3];
    float fxi = floorf(xf), fyi = floorf(yf), fzi = floorf(zf);
    int xi = (int)fxi, yi = (int)fyi, zi = (int)fzi;
    float frx = xf - fxi, fry = yf - fyi, frz = zf - fzi;

    float acc = 0.f, wsum = 0.f;
#pragma unroll
    for (int g = 0; g < 8; g++) {
        int gx = (g >> 2) & 1, gy = (g >> 1) & 1, gz = g & 1;
        int cx = xi + gx, cy = yi + gy, cz = zi + gz;
        bool inb = (cx >= 0) & (cx < R) & (cy >= 0) & (cy < R) & (cz >= 0) & (cz < R);
        if (!inb) continue;
        int key = ((b * R + cx) * R + cy) * R + cz;
        int idx = lookup_idx(key, keys, nnum, table_lim);
        if (idx >= 0) {
            float w = (gx ? frx : 1.0f - frx) *
                      (gy ? fry : 1.0f - fry) *
                      (gz ? frz : 1.0f - frz);
            acc  += w * data[(size_t)idx * C + c];
            wsum += w;
        }
    }
    out[(size_t)p * C + c] = acc / (wsum + 1e-12f);
}

extern "C" void kernel_launch(void* const* d_in, const int* in_sizes, int n_in,
                              void* d_out, int out_size) {
    const float* data      = (const float*)d_in[0];
    const float* pts       = (const float*)d_in[1];
    const int*   node_keys = (const int*)d_in[2];
    const int*   depth_p   = (const int*)d_in[3];
    float*       out       = (float*)d_out;

    int npts = in_sizes[1] / 4;
    int nnum = in_sizes[2];
    int C    = (nnum > 0) ? in_sizes[0] / nnum : 32;

    // Rebuild inverse table each launch (graph-deterministic).
    clear_table_k<<<512, 256>>>(depth_p);
    build_table_k<<<256, 256>>>(node_keys, nnum, depth_p);

    if (C % 4 == 0 && (C / 4) <= 32) {
        int cgroups = C / 4;                  // 8 for C=32
        int pperb   = 256 / cgroups;          // 32 points per block
        dim3 block(cgroups, pperb);
        int blocks = (npts + pperb - 1) / pperb;
        interp_vec_k<<<blocks, block>>>((const float4*)data, (const float4*)pts,
                                        node_keys, nnum, depth_p,
                                        (float4*)out, npts, cgroups);
    } else {
        long long total = (long long)npts * C;
        int blocks = (int)((total + 255) / 256);
        interp_scalar_k<<<blocks, 256>>>(data, pts, node_keys, nnum, depth_p,
                                         out, npts, C);
    }
}